// round 5
// baseline (speedup 1.0000x reference)
#include <cuda_runtime.h>

// ---------------------------------------------------------------------------
// DoG 3D: out = blur(x, sigma=1.0, k=9) - blur(x, sigma=1.6, k=15)
// Separable, replicate boundary. fp32 float2-packed intermediates.
//   pass_wh: W-conv + H-conv in smem tile, packed f32x2 FMA throughout.
//   pass_d : D-conv + fused subtract, packed loads/FMA/stores.
// ---------------------------------------------------------------------------

#define NB 2
#define L 160
#define WP2 80                // 160/2 packed pairs per row
#define SLAB (L * L)          // 25600
#define VOL (L * L * L)       // 4096000
#define TOT (NB * VOL)        // 8192000

typedef unsigned long long u64;

// fp32 intermediates, packed as pairs along w.
__device__ u64 g_lo2[TOT / 2];
__device__ u64 g_hi2[TOT / 2];

// Normalized 1D gaussian weights (each sums to 1).
#define KL0 1.338302e-04f
#define KL1 4.431861e-03f
#define KL2 5.399113e-02f
#define KL3 2.419714e-01f
#define KL4 3.989435e-01f

#define KH0 1.739620e-05f
#define KH1 2.203730e-04f
#define KH2 1.888900e-03f
#define KH3 1.095520e-02f
#define KH4 4.299160e-02f
#define KH5 1.141557e-01f
#define KH6 2.051009e-01f
#define KH7 2.493392e-01f

__device__ __forceinline__ float klw(int i) {
    const float v[9] = {KL0, KL1, KL2, KL3, KL4, KL3, KL2, KL1, KL0};
    return v[i];
}
__device__ __forceinline__ float khw(int i) {
    const float v[15] = {KH0, KH1, KH2, KH3, KH4, KH5, KH6, KH7,
                         KH6, KH5, KH4, KH3, KH2, KH1, KH0};
    return v[i];
}

// ---------------- packed f32x2 helpers -------------------------------------
__device__ __forceinline__ u64 pk(float a, float b) {
    u64 r;
    asm("mov.b64 %0, {%1, %2};" : "=l"(r) : "f"(a), "f"(b));
    return r;
}
__device__ __forceinline__ void upk(u64 v, float& a, float& b) {
    asm("mov.b64 {%0, %1}, %2;" : "=f"(a), "=f"(b) : "l"(v));
}
__device__ __forceinline__ void fma2(u64& d, u64 a, u64 b) {
    asm("fma.rn.f32x2 %0, %1, %2, %0;" : "+l"(d) : "l"(a), "l"(b));
}

// ---------------- fused pass: conv along W then H ---------------------------
#define HT 32
#define ROWS (HT + 14)        // 46
#define PADW 176              // input halo row, padded

__global__ void __launch_bounds__(320, 2) pass_wh_kernel(const float* __restrict__ x) {
    extern __shared__ float sm[];
    float* s_in = sm;                           // ROWS * PADW floats
    u64* s_lo = (u64*)(sm + ROWS * PADW);       // ROWS * WP2 pairs
    u64* s_hi = s_lo + ROWS * WP2;              // ROWS * WP2 pairs

    const int b = blockIdx.x;
    const int slab = b / 5;                     // n*160 + d
    const int tile = b % 5;
    const int h0 = tile * HT - 7;
    const int base_g = slab * SLAB;
    const int tid = threadIdx.x;

    // ---- load input tile with replicate clamp in h and w -------------------
    for (int idx = tid; idx < ROWS * 174; idx += 320) {
        const int r = idx / 174;
        const int c = idx % 174;                // c-7 = w
        int h = h0 + r;
        h = h < 0 ? 0 : (h > (L - 1) ? (L - 1) : h);
        int w = c - 7;
        w = w < 0 ? 0 : (w > (L - 1) ? (L - 1) : w);
        s_in[r * PADW + c] = x[base_g + h * L + w];
    }
    __syncthreads();

    // ---- W-conv: thread -> one packed out-pair per visited row -------------
    // out pair w = {2wp, 2wp+1}; input cols c = 2wp .. 2wp+15 (c-7 = w-7..w+8)
    {
        const int wp = tid % WP2;
        const int rg = tid / WP2;               // 0..3
        for (int r = rg; r < ROWS; r += 4) {
            const float* row = &s_in[r * PADW + 2 * wp];
            u64 P[8];
#pragma unroll
            for (int j = 0; j < 8; ++j) P[j] = *(const u64*)&row[2 * j];
            float v[16];
#pragma unroll
            for (int j = 0; j < 8; ++j) upk(P[j], v[2 * j], v[2 * j + 1]);
            u64 M[7];
#pragma unroll
            for (int j = 0; j < 7; ++j) M[j] = pk(v[2 * j + 1], v[2 * j + 2]);
            // pair starting at offset s: s even -> P[s/2], s odd -> M[s/2]
#define PAIR(s) (((s) & 1) ? M[(s) >> 1] : P[(s) >> 1])
            u64 aH = 0, aL = 0;
#pragma unroll
            for (int t = 0; t < 15; ++t) fma2(aH, PAIR(t), pk(khw(t), khw(t)));
#pragma unroll
            for (int t = 0; t < 9; ++t)  fma2(aL, PAIR(t + 3), pk(klw(t), klw(t)));
#undef PAIR
            s_lo[r * WP2 + wp] = aL;
            s_hi[r * WP2 + wp] = aH;
        }
    }
    __syncthreads();

    // ---- H-conv: thread -> packed w-pair, 8 h-outputs ----------------------
    {
        const int wp = tid % WP2;
        const int seg = tid / WP2;              // 0..3
        const int oh0 = seg * 8;                // local output h base (0..24)
        const int gbase = (u64)0, _unused = gbase + _unused; // silence none
        const int gidx0 = (base_g + (tile * HT + oh0) * L) / 2 + wp;

        // high: rows oh0 .. oh0+21
        {
            u64 B[22];
#pragma unroll
            for (int j = 0; j < 22; ++j) B[j] = s_hi[(oh0 + j) * WP2 + wp];
            u64 acc[8] = {0, 0, 0, 0, 0, 0, 0, 0};
#pragma unroll
            for (int t = 0; t < 15; ++t) {
                const u64 wgt = pk(khw(t), khw(t));
#pragma unroll
                for (int i = 0; i < 8; ++i) fma2(acc[i], B[i + t], wgt);
            }
#pragma unroll
            for (int i = 0; i < 8; ++i) g_hi2[gidx0 + i * WP2] = acc[i];
        }
        // low: rows oh0+3 .. oh0+18
        {
            u64 A[16];
#pragma unroll
            for (int j = 0; j < 16; ++j) A[j] = s_lo[(oh0 + 3 + j) * WP2 + wp];
            u64 acc[8] = {0, 0, 0, 0, 0, 0, 0, 0};
#pragma unroll
            for (int t = 0; t < 9; ++t) {
                const u64 wgt = pk(klw(t), klw(t));
#pragma unroll
                for (int i = 0; i < 8; ++i) fma2(acc[i], A[i + t], wgt);
            }
#pragma unroll
            for (int i = 0; i < 8; ++i) g_lo2[gidx0 + i * WP2] = acc[i];
        }
    }
}

// ---------------- pass D: conv along D + fused subtract --------------------
// thread -> packed w-pair, 8 d-outputs. acc = low - high via negated weights.
__global__ void __launch_bounds__(256) pass_d_kernel(float* __restrict__ out) {
    const int tid = blockIdx.x * 256 + threadIdx.x;   // < 512000
    const int wp = tid % WP2;
    const int rest = tid / WP2;
    const int h = rest % L;
    const int r2 = rest / L;        // 0..39
    const int seg = r2 % 20;
    const int n = r2 / 20;
    const int d0 = seg * 8;
    const int base2 = (n * VOL) / 2 + h * WP2 + wp;   // in pairs
    const int ps = SLAB / 2;                          // plane stride in pairs

    u64 acc[8] = {0, 0, 0, 0, 0, 0, 0, 0};
    // low taps (+klw): d = d0-4 .. d0+11
    {
        u64 A[16];
#pragma unroll
        for (int j = 0; j < 16; ++j) {
            int d = d0 + j - 4;
            d = d < 0 ? 0 : (d > (L - 1) ? (L - 1) : d);
            A[j] = g_lo2[base2 + d * ps];
        }
#pragma unroll
        for (int t = 0; t < 9; ++t) {
            const u64 wgt = pk(klw(t), klw(t));
#pragma unroll
            for (int i = 0; i < 8; ++i) fma2(acc[i], A[i + t], wgt);
        }
    }
    // high taps (-khw): d = d0-7 .. d0+14
    {
        u64 B[22];
#pragma unroll
        for (int j = 0; j < 22; ++j) {
            int d = d0 + j - 7;
            d = d < 0 ? 0 : (d > (L - 1) ? (L - 1) : d);
            B[j] = g_hi2[base2 + d * ps];
        }
#pragma unroll
        for (int t = 0; t < 15; ++t) {
            const u64 wgt = pk(-khw(t), -khw(t));
#pragma unroll
            for (int i = 0; i < 8; ++i) fma2(acc[i], B[i + t], wgt);
        }
    }
#pragma unroll
    for (int i = 0; i < 8; ++i)
        *(u64*)&out[2 * (base2 + (d0 + i) * ps)] = acc[i];
}

extern "C" void kernel_launch(void* const* d_in, const int* in_sizes, int n_in,
                              void* d_out, int out_size) {
    const float* x = (const float*)d_in[0];
    float* out = (float*)d_out;

    const int smem = (ROWS * PADW + 2 * ROWS * L) * (int)sizeof(float); // 91264B
    static int attr_done = 0;
    if (!attr_done) {
        cudaFuncSetAttribute(pass_wh_kernel,
                             cudaFuncAttributeMaxDynamicSharedMemorySize, smem);
        attr_done = 1;
    }

    pass_wh_kernel<<<320 * 5, 320, smem>>>(x);
    pass_d_kernel<<<2000, 256>>>(out);
}

// round 6
// speedup vs baseline: 1.3170x; 1.3170x over previous
#include <cuda_runtime.h>

// ---------------------------------------------------------------------------
// DoG 3D: out = blur(x, sigma=1.0, k=9) - blur(x, sigma=1.6, k=15)
// Separable, replicate boundary.
//   pass_wh: W-conv + H-conv fused in smem tile (lo overwrites s_in in place),
//            scalar FFMA with immediate weights throughout.
//   pass_d : D-conv + fused subtract (negated high weights), float2 I/O.
// ---------------------------------------------------------------------------

#define NB 2
#define L 160
#define WP2 80                 // packed pairs per row
#define SLAB (L * L)           // 25600
#define VOL (L * L * L)        // 4096000
#define TOT (NB * VOL)         // 8192000

// fp32 intermediates, packed as float2 pairs along w.
__device__ float2 g_lo2[TOT / 2];
__device__ float2 g_hi2[TOT / 2];

// Normalized 1D gaussian weights (each sums to 1).
#define KL0 1.338302e-04f
#define KL1 4.431861e-03f
#define KL2 5.399113e-02f
#define KL3 2.419714e-01f
#define KL4 3.989435e-01f

#define KH0 1.739620e-05f
#define KH1 2.203730e-04f
#define KH2 1.888900e-03f
#define KH3 1.095520e-02f
#define KH4 4.299160e-02f
#define KH5 1.141557e-01f
#define KH6 2.051009e-01f
#define KH7 2.493392e-01f

__device__ __forceinline__ float klw(int i) {
    const float v[9] = {KL0, KL1, KL2, KL3, KL4, KL3, KL2, KL1, KL0};
    return v[i];
}
__device__ __forceinline__ float khw(int i) {
    const float v[15] = {KH0, KH1, KH2, KH3, KH4, KH5, KH6, KH7,
                         KH6, KH5, KH4, KH3, KH2, KH1, KH0};
    return v[i];
}

// ---------------- fused pass: conv along W then H ---------------------------
#define HT 32
#define ROWS 46                 // HT + 14 halo rows
#define PADW 176                // input layout: col c = w + 8, c in 0..174
#define SM_IN_F (ROWS * PADW)   // 8096 floats (later reused: lo at col w)
#define SM_HI_F (ROWS * L)      // 7360 floats
#define SMEM_BYTES ((SM_IN_F + SM_HI_F) * 4)   // 61824 B -> 3 blocks/SM

__global__ void __launch_bounds__(320, 3) pass_wh_kernel(const float* __restrict__ x) {
    extern __shared__ float sm[];
    float* s_in = sm;               // input (+8 col offset); lo written in place
    float* s_hi = sm + SM_IN_F;     // W-conv high result, stride L

    const int b = blockIdx.x;
    const int slab = b / 5;         // n*160 + d
    const int tile = b % 5;
    const int h0 = tile * HT - 7;
    const int base_g = slab * SLAB;
    const int tid = threadIdx.x;
    const int wp = tid % WP2;       // 0..79
    const int rg = tid / WP2;       // 0..3

    // ---- loader: interior float2 pairs; r = 4k + rg, pair index = wp -------
#pragma unroll
    for (int k = 0; k < 12; ++k) {
        const int r = 4 * k + rg;
        if (r < ROWS) {
            int h = h0 + r;
            h = h < 0 ? 0 : (h > (L - 1) ? (L - 1) : h);
            const float2 v = *(const float2*)&x[base_g + h * L + 2 * wp];
            *(float2*)&s_in[r * PADW + 8 + 2 * wp] = v;
        }
    }
    // halo columns: left (w<0 -> x[h][0]) and right (w>159 -> x[h][159])
    if (tid < 92) {
        const int r = tid >> 1;
        int h = h0 + r;
        h = h < 0 ? 0 : (h > (L - 1) ? (L - 1) : h);
        if ((tid & 1) == 0) {
            const float v = x[base_g + h * L];
            const float2 vv = make_float2(v, v);
            *(float2*)&s_in[r * PADW + 0] = vv;
            *(float2*)&s_in[r * PADW + 2] = vv;
            *(float2*)&s_in[r * PADW + 4] = vv;
            *(float2*)&s_in[r * PADW + 6] = vv;
        } else {
            const float v = x[base_g + h * L + (L - 1)];
            const float2 vv = make_float2(v, v);
            *(float2*)&s_in[r * PADW + 168] = vv;
            *(float2*)&s_in[r * PADW + 170] = vv;
            *(float2*)&s_in[r * PADW + 172] = vv;
            s_in[r * PADW + 174] = v;
        }
    }
    __syncthreads();

    // ---- W-conv, software-pipelined, lo written IN PLACE over s_in ---------
    // Round k handles row r = 4k+rg. Window k (between BARs) does:
    //   write row 4k+rg  (cols 2wp..2wp+1, plain w space)
    //   read  row 4(k+1)+rg (+8 offset space)  -- disjoint rows, race-free.
    float v[18];
    {
        const float* row = &s_in[rg * PADW + 2 * wp];
#pragma unroll
        for (int m = 0; m < 9; ++m) {
            const float2 p = *(const float2*)&row[2 * m];
            v[2 * m] = p.x;
            v[2 * m + 1] = p.y;
        }
    }
    __syncthreads();
#pragma unroll
    for (int k = 0; k < 12; ++k) {
        const int r = 4 * k + rg;
        if (r < ROWS) {
            float sH0 = 0.f, sH1 = 0.f, sL0 = 0.f, sL1 = 0.f;
#pragma unroll
            for (int t = 0; t < 15; ++t) {
                sH0 = fmaf(v[t + 1], khw(t), sH0);
                sH1 = fmaf(v[t + 2], khw(t), sH1);
            }
#pragma unroll
            for (int t = 0; t < 9; ++t) {
                sL0 = fmaf(v[t + 4], klw(t), sL0);
                sL1 = fmaf(v[t + 5], klw(t), sL1);
            }
            *(float2*)&s_in[r * PADW + 2 * wp] = make_float2(sL0, sL1);
            *(float2*)&s_hi[r * L + 2 * wp] = make_float2(sH0, sH1);
        }
        if (k < 11) {
            const int rn = 4 * (k + 1) + rg;
            if (rn < ROWS) {
                const float* row = &s_in[rn * PADW + 2 * wp];
#pragma unroll
                for (int m = 0; m < 9; ++m) {
                    const float2 p = *(const float2*)&row[2 * m];
                    v[2 * m] = p.x;
                    v[2 * m + 1] = p.y;
                }
            }
        }
        __syncthreads();
    }

    // ---- H-conv: w-pair per thread, 8 h-outputs, j-streaming ---------------
    {
        const int oh0 = rg * 8;     // local output h base: 0,8,16,24
        float2 accH[8];
#pragma unroll
        for (int i = 0; i < 8; ++i) accH[i] = make_float2(0.f, 0.f);
#pragma unroll
        for (int j = 0; j < 22; ++j) {
            const float2 bp = *(const float2*)&s_hi[(oh0 + j) * L + 2 * wp];
#pragma unroll
            for (int i = 0; i < 8; ++i) {
                const int t = j - i;
                if (t >= 0 && t < 15) {
                    accH[i].x = fmaf(bp.x, khw(t), accH[i].x);
                    accH[i].y = fmaf(bp.y, khw(t), accH[i].y);
                }
            }
        }
        float2 accL[8];
#pragma unroll
        for (int i = 0; i < 8; ++i) accL[i] = make_float2(0.f, 0.f);
#pragma unroll
        for (int j = 0; j < 16; ++j) {
            const float2 ap = *(const float2*)&s_in[(oh0 + 3 + j) * PADW + 2 * wp];
#pragma unroll
            for (int i = 0; i < 8; ++i) {
                const int t = j - i;
                if (t >= 0 && t < 9) {
                    accL[i].x = fmaf(ap.x, klw(t), accL[i].x);
                    accL[i].y = fmaf(ap.y, klw(t), accL[i].y);
                }
            }
        }
        const int gp0 = (base_g + (tile * HT + oh0) * L) / 2 + wp;
#pragma unroll
        for (int i = 0; i < 8; ++i) {
            g_hi2[gp0 + i * WP2] = accH[i];
            g_lo2[gp0 + i * WP2] = accL[i];
        }
    }
}

// ---------------- pass D: conv along D + fused subtract --------------------
__global__ void __launch_bounds__(256, 5) pass_d_kernel(float* __restrict__ out) {
    const int tid = blockIdx.x * 256 + threadIdx.x;   // < 512000
    const int wp = tid % WP2;
    const int rest = tid / WP2;
    const int h = rest % L;
    const int r2 = rest / L;        // 0..39
    const int seg = r2 % 20;
    const int n = r2 / 20;
    const int d0 = seg * 8;
    const int base2 = (n * VOL) / 2 + h * WP2 + wp;   // float2 index
    const int ps = SLAB / 2;                          // plane stride in pairs

    float2 acc[8];
#pragma unroll
    for (int i = 0; i < 8; ++i) acc[i] = make_float2(0.f, 0.f);

    // low taps (+klw): rows d0-4 .. d0+11
    {
        float2 A[16];
#pragma unroll
        for (int j = 0; j < 16; ++j) {
            int d = d0 + j - 4;
            d = d < 0 ? 0 : (d > (L - 1) ? (L - 1) : d);
            A[j] = g_lo2[base2 + d * ps];
        }
#pragma unroll
        for (int t = 0; t < 9; ++t) {
#pragma unroll
            for (int i = 0; i < 8; ++i) {
                acc[i].x = fmaf(A[i + t].x, klw(t), acc[i].x);
                acc[i].y = fmaf(A[i + t].y, klw(t), acc[i].y);
            }
        }
    }
    // high taps (-khw): rows d0-7 .. d0+14 -> acc = low - high
    {
        float2 B[22];
#pragma unroll
        for (int j = 0; j < 22; ++j) {
            int d = d0 + j - 7;
            d = d < 0 ? 0 : (d > (L - 1) ? (L - 1) : d);
            B[j] = g_hi2[base2 + d * ps];
        }
#pragma unroll
        for (int t = 0; t < 15; ++t) {
#pragma unroll
            for (int i = 0; i < 8; ++i) {
                acc[i].x = fmaf(B[i + t].x, -khw(t), acc[i].x);
                acc[i].y = fmaf(B[i + t].y, -khw(t), acc[i].y);
            }
        }
    }
#pragma unroll
    for (int i = 0; i < 8; ++i)
        *(float2*)&out[2 * (base2 + (d0 + i) * ps)] = acc[i];
}

extern "C" void kernel_launch(void* const* d_in, const int* in_sizes, int n_in,
                              void* d_out, int out_size) {
    const float* x = (const float*)d_in[0];
    float* out = (float*)d_out;

    static int attr_done = 0;
    if (!attr_done) {
        cudaFuncSetAttribute(pass_wh_kernel,
                             cudaFuncAttributeMaxDynamicSharedMemorySize, SMEM_BYTES);
        attr_done = 1;
    }

    pass_wh_kernel<<<320 * 5, 320, SMEM_BYTES>>>(x);
    pass_d_kernel<<<2000, 256>>>(out);
}

// round 10
// speedup vs baseline: 1.6425x; 1.2471x over previous
#include <cuda_runtime.h>
#include <cuda_fp16.h>

// ---------------------------------------------------------------------------
// DoG 3D: out = blur(x, sigma=1.0, k=9) - blur(x, sigma=1.6, k=15)
// Separable, replicate boundary.
//   pass_wh: W-conv (float4 smem loads, in-place lo) + H-conv; writes
//            interleaved fp16 (lo01|hi01) u64 per w-pair.
//   pass_d : D-conv + fused subtract; 22 LDG.64 per thread, fp16->fp32 cvt.
// ---------------------------------------------------------------------------

#define NB 2
#define L 160
#define WP2 80                 // w-pairs per row
#define SLAB (L * L)           // 25600
#define VOL (L * L * L)        // 4096000
#define TOT (NB * VOL)         // 8192000

typedef unsigned long long u64;
typedef unsigned int u32;

// Interleaved fp16 intermediates: per w-pair, low 32b = lo01 half2, high = hi01.
__device__ u64 g_wh[TOT / 2];

// Normalized 1D gaussian weights (each sums to 1).
#define KL0 1.338302e-04f
#define KL1 4.431861e-03f
#define KL2 5.399113e-02f
#define KL3 2.419714e-01f
#define KL4 3.989435e-01f

#define KH0 1.739620e-05f
#define KH1 2.203730e-04f
#define KH2 1.888900e-03f
#define KH3 1.095520e-02f
#define KH4 4.299160e-02f
#define KH5 1.141557e-01f
#define KH6 2.051009e-01f
#define KH7 2.493392e-01f

__device__ __forceinline__ float klw(int i) {
    const float v[9] = {KL0, KL1, KL2, KL3, KL4, KL3, KL2, KL1, KL0};
    return v[i];
}
__device__ __forceinline__ float khw(int i) {
    const float v[15] = {KH0, KH1, KH2, KH3, KH4, KH5, KH6, KH7,
                         KH6, KH5, KH4, KH3, KH2, KH1, KH0};
    return v[i];
}

// ---------------- fused pass: conv along W then H ---------------------------
#define HT 32
#define ROWS 46                 // HT + 14 halo rows
#define PADW 176                // input col c = w + 8, c in 0..174
#define SM_IN_F (ROWS * PADW)   // 8096 floats; lo overwrites cols 0..159 (w-space)
#define SM_HI_F (ROWS * L)      // 7360 floats
#define SMEM_BYTES ((SM_IN_F + SM_HI_F) * 4)   // 61824 B -> 3 blocks/SM

__global__ void __launch_bounds__(320, 3) pass_wh_kernel(const float* __restrict__ x) {
    extern __shared__ float sm[];
    float* s_in = sm;               // input (+8 col offset); lo written in place
    float* s_hi = sm + SM_IN_F;

    const int b = blockIdx.x;
    const int slab = b / 5;         // n*160 + d
    const int tile = b % 5;
    const int h0 = tile * HT - 7;
    const int base_g = slab * SLAB;
    const int tid = threadIdx.x;

    // ---- loader: interior float2 pairs + replicated halo columns ----------
    {
        const int wp = tid % WP2;
        const int rg = tid / WP2;   // 0..3
#pragma unroll
        for (int k = 0; k < 12; ++k) {
            const int r = 4 * k + rg;
            if (r < ROWS) {
                int h = h0 + r;
                h = h < 0 ? 0 : (h > (L - 1) ? (L - 1) : h);
                const float2 v = *(const float2*)&x[base_g + h * L + 2 * wp];
                *(float2*)&s_in[r * PADW + 8 + 2 * wp] = v;
            }
        }
        if (tid < 92) {
            const int r = tid >> 1;
            int h = h0 + r;
            h = h < 0 ? 0 : (h > (L - 1) ? (L - 1) : h);
            if ((tid & 1) == 0) {
                const float v = x[base_g + h * L];
                const float2 vv = make_float2(v, v);
                *(float2*)&s_in[r * PADW + 0] = vv;
                *(float2*)&s_in[r * PADW + 2] = vv;
                *(float2*)&s_in[r * PADW + 4] = vv;
                *(float2*)&s_in[r * PADW + 6] = vv;
            } else {
                const float v = x[base_g + h * L + (L - 1)];
                const float2 vv = make_float2(v, v);
                *(float2*)&s_in[r * PADW + 168] = vv;
                *(float2*)&s_in[r * PADW + 170] = vv;
                *(float2*)&s_in[r * PADW + 172] = vv;
                s_in[r * PADW + 174] = v;
            }
        }
    }
    __syncthreads();

    // ---- W-conv: 4 outputs/thread/row, float4 smem loads, in-place lo ------
    // thread: w0 = 4*(tid%40), row group rg8 = tid/40 (rows r = 8k + rg8).
    // taps for outputs w0..w0+3: offset cols w0+1 .. w0+18  ->  v[1..18] where
    // v[m] = s_in[r*PADW + w0 + m], loaded as 5 float4 (cols w0..w0+19).
    {
        const int w0 = 4 * (tid % 40);
        const int rg8 = tid / 40;   // 0..7
        float v[20];
        // preload round 0
        {
            const int r = rg8;      // < 46 always
            const float* row = &s_in[r * PADW + w0];
#pragma unroll
            for (int m = 0; m < 5; ++m) {
                const float4 p = *(const float4*)&row[4 * m];
                v[4 * m] = p.x; v[4 * m + 1] = p.y;
                v[4 * m + 2] = p.z; v[4 * m + 3] = p.w;
            }
        }
        __syncthreads();
#pragma unroll
        for (int k = 0; k < 6; ++k) {
            const int r = 8 * k + rg8;
            if (r < ROWS) {
                float sH[4] = {0.f, 0.f, 0.f, 0.f};
                float sL[4] = {0.f, 0.f, 0.f, 0.f};
#pragma unroll
                for (int t = 0; t < 15; ++t) {
#pragma unroll
                    for (int o = 0; o < 4; ++o)
                        sH[o] = fmaf(v[o + 1 + t], khw(t), sH[o]);
                }
#pragma unroll
                for (int t = 0; t < 9; ++t) {
#pragma unroll
                    for (int o = 0; o < 4; ++o)
                        sL[o] = fmaf(v[o + 4 + t], klw(t), sL[o]);
                }
                *(float4*)&s_in[r * PADW + w0] =
                    make_float4(sL[0], sL[1], sL[2], sL[3]);
                *(float4*)&s_hi[r * L + w0] =
                    make_float4(sH[0], sH[1], sH[2], sH[3]);
            }
            if (k < 5) {
                const int rn = 8 * (k + 1) + rg8;
                if (rn < ROWS) {
                    const float* row = &s_in[rn * PADW + w0];
#pragma unroll
                    for (int m = 0; m < 5; ++m) {
                        const float4 p = *(const float4*)&row[4 * m];
                        v[4 * m] = p.x; v[4 * m + 1] = p.y;
                        v[4 * m + 2] = p.z; v[4 * m + 3] = p.w;
                    }
                }
            }
            __syncthreads();
        }
    }

    // ---- H-conv: w-pair per thread, 8 h-outputs, interleaved fp16 store ----
    {
        const int wp = tid % WP2;
        const int rg = tid / WP2;   // 0..3
        const int oh0 = rg * 8;

        float2 accH[8];
#pragma unroll
        for (int i = 0; i < 8; ++i) accH[i] = make_float2(0.f, 0.f);
#pragma unroll
        for (int j = 0; j < 22; ++j) {
            const float2 bp = *(const float2*)&s_hi[(oh0 + j) * L + 2 * wp];
#pragma unroll
            for (int i = 0; i < 8; ++i) {
                const int t = j - i;
                if (t >= 0 && t < 15) {
                    accH[i].x = fmaf(bp.x, khw(t), accH[i].x);
                    accH[i].y = fmaf(bp.y, khw(t), accH[i].y);
                }
            }
        }
        float2 accL[8];
#pragma unroll
        for (int i = 0; i < 8; ++i) accL[i] = make_float2(0.f, 0.f);
#pragma unroll
        for (int j = 0; j < 16; ++j) {
            const float2 ap = *(const float2*)&s_in[(oh0 + 3 + j) * PADW + 2 * wp];
#pragma unroll
            for (int i = 0; i < 8; ++i) {
                const int t = j - i;
                if (t >= 0 && t < 9) {
                    accL[i].x = fmaf(ap.x, klw(t), accL[i].x);
                    accL[i].y = fmaf(ap.y, klw(t), accL[i].y);
                }
            }
        }
        const int gp0 = (base_g + (tile * HT + oh0) * L) / 2 + wp;
#pragma unroll
        for (int i = 0; i < 8; ++i) {
            const __half2 hl = __floats2half2_rn(accL[i].x, accL[i].y);
            const __half2 hh = __floats2half2_rn(accH[i].x, accH[i].y);
            const u32 a = *(const u32*)&hl;
            const u32 bq = *(const u32*)&hh;
            g_wh[gp0 + i * WP2] = (u64)a | ((u64)bq << 32);
        }
    }
}

// ---------------- pass D: conv along D + fused subtract --------------------
// thread -> w-pair, 8 d-outputs. Loads 22 interleaved u64 taps (2 batches).
__global__ void __launch_bounds__(256, 4) pass_d_kernel(float* __restrict__ out) {
    const int tid = blockIdx.x * 256 + threadIdx.x;   // < 512000
    const int wp = tid % WP2;
    const int rest = tid / WP2;
    const int h = rest % L;
    const int r2 = rest / L;        // 0..39
    const int seg = r2 % 20;
    const int n = r2 / 20;
    const int d0 = seg * 8;
    const int base2 = (n * VOL) / 2 + h * WP2 + wp;   // pair index
    const int ps = SLAB / 2;

    float2 acc[8];
#pragma unroll
    for (int i = 0; i < 8; ++i) acc[i] = make_float2(0.f, 0.f);

#pragma unroll
    for (int half = 0; half < 2; ++half) {
        const int j0 = half * 11;
        u64 C[11];
#pragma unroll
        for (int jj = 0; jj < 11; ++jj) {
            int d = d0 + j0 + jj - 7;
            d = d < 0 ? 0 : (d > (L - 1) ? (L - 1) : d);
            C[jj] = g_wh[base2 + d * ps];
        }
#pragma unroll
        for (int jj = 0; jj < 11; ++jj) {
            const int j = j0 + jj;
            const u32 a = (u32)C[jj];
            const u32 bq = (u32)(C[jj] >> 32);
            const float2 flo = __half22float2(*(const __half2*)&a);
            const float2 fhi = __half22float2(*(const __half2*)&bq);
#pragma unroll
            for (int i = 0; i < 8; ++i) {
                const int th = j - i;          // high tap
                if (th >= 0 && th < 15) {
                    acc[i].x = fmaf(fhi.x, -khw(th), acc[i].x);
                    acc[i].y = fmaf(fhi.y, -khw(th), acc[i].y);
                }
                const int tl = j - 3 - i;      // low tap
                if (tl >= 0 && tl < 9) {
                    acc[i].x = fmaf(flo.x, klw(tl), acc[i].x);
                    acc[i].y = fmaf(flo.y, klw(tl), acc[i].y);
                }
            }
        }
    }
#pragma unroll
    for (int i = 0; i < 8; ++i)
        *(float2*)&out[2 * (base2 + (d0 + i) * ps)] = acc[i];
}

extern "C" void kernel_launch(void* const* d_in, const int* in_sizes, int n_in,
                              void* d_out, int out_size) {
    const float* x = (const float*)d_in[0];
    float* out = (float*)d_out;

    static int attr_done = 0;
    if (!attr_done) {
        cudaFuncSetAttribute(pass_wh_kernel,
                             cudaFuncAttributeMaxDynamicSharedMemorySize, SMEM_BYTES);
        attr_done = 1;
    }

    pass_wh_kernel<<<320 * 5, 320, SMEM_BYTES>>>(x);
    pass_d_kernel<<<2000, 256>>>(out);
}